// round 14
// baseline (speedup 1.0000x reference)
#include <cuda_runtime.h>
#include <cuda_fp16.h>
#include <cstdint>

#define N_NODES_MAX 50000
#define N_EDGES_MAX 524288
#define NODE_DIM    128
#define HIDDEN      256
#define NCOLS       1024
#define NROW_PAD    50432   // 197*256, >= N_NODES_MAX+1

// Table column layout: [0:256)=seg0 (p1 row), [256:512)=seg2 (p2 row),
//                      [512:768)=seg1 (p1 col), [768:1024)=seg3 (p2 col)

__device__ __half g_table[(size_t)N_NODES_MAX * NCOLS];   // 102.4 MB
__device__ __half g_Xh[(size_t)N_NODES_MAX * NODE_DIM];
__device__ __half g_WTh[NCOLS * NODE_DIM];
__device__ __half g_ch[HIDDEN];
__device__ __half g_w2h[HIDDEN];
__device__ int    g_is64;

// counting-sort scratch
__device__ int g_count[NROW_PAD];
__device__ int g_pscan[NROW_PAD];
__device__ int g_rowStart[NROW_PAD];
__device__ int g_fill[NROW_PAD];
__device__ int g_blockSum[256];
__device__ int g_blockOff[256];
__device__ uint32_t g_sCol[N_EDGES_MAX];
__device__ int      g_sEid[N_EDGES_MAX];

__device__ __forceinline__ uint32_t smem_u32(const void* p) {
    uint32_t a;
    asm("{ .reg .u64 t; cvta.to.shared.u64 t, %1; cvt.u32.u64 %0, t; }" : "=r"(a) : "l"(p));
    return a;
}
__device__ __forceinline__ void ldsm_x4(uint32_t& r0, uint32_t& r1, uint32_t& r2, uint32_t& r3,
                                        uint32_t addr) {
    asm volatile("ldmatrix.sync.aligned.m8n8.x4.shared.b16 {%0,%1,%2,%3}, [%4];"
                 : "=r"(r0), "=r"(r1), "=r"(r2), "=r"(r3) : "r"(addr));
}
__device__ __forceinline__ void mma16816(float* c, const uint32_t* a, uint32_t b0, uint32_t b1) {
    asm volatile("mma.sync.aligned.m16n8k16.row.col.f32.f16.f16.f32 "
                 "{%0,%1,%2,%3}, {%4,%5,%6,%7}, {%8,%9}, {%0,%1,%2,%3};"
                 : "+f"(c[0]), "+f"(c[1]), "+f"(c[2]), "+f"(c[3])
                 : "r"(a[0]), "r"(a[1]), "r"(a[2]), "r"(a[3]), "r"(b0), "r"(b1));
}
#define CP16(dst, src) \
    asm volatile("cp.async.cg.shared.global [%0], [%1], 16;" :: "r"(dst), "l"(src))
#define CP16P(dst, src, p) \
    asm volatile("{ .reg .pred q; setp.ne.b32 q, %2, 0;\n\t" \
                 "@q cp.async.cg.shared.global [%0], [%1], 16; }" \
                 :: "r"(dst), "l"(src), "r"(p))
#define CP_COMMIT  asm volatile("cp.async.commit_group;")
#define CP_WAIT1   asm volatile("cp.async.wait_group 1;")

// ---------------------------------------------------------------------------
// Fused prep (+zero of sort counters in extra trailing blocks)
// ---------------------------------------------------------------------------
__global__ void prep_all_kernel(const float* __restrict__ X,
                                const float* __restrict__ W1, const float* __restrict__ b1,
                                const float* __restrict__ gamma, const float* __restrict__ beta,
                                const float* __restrict__ mean, const float* __restrict__ var,
                                const float* __restrict__ W2,
                                const int* __restrict__ idx32, int nx, int total4) {
    int b = blockIdx.x;
    int tid = threadIdx.x;
    if (b < 512) {
        int i = b * 256 + tid;
        int n = i >> 7;
        int k = i & 127;
        int h = n & 255;
        int grp = n >> 8;
        int srcRow;
        if (grp == 0)      srcRow = k;
        else if (grp == 1) srcRow = k + 16;
        else if (grp == 2) srcRow = 128 + k;
        else               srcRow = (k + 144) & 255;
        float s = gamma[h] * rsqrtf(var[h] + 1e-5f);
        g_WTh[i] = __float2half_rn(W1[srcRow * 256 + h] * s);
    } else if (b < 512 + nx) {
        int i = (b - 512) * 256 + tid;
        if (i < total4) {
            float4 v = *(const float4*)(X + i * 4);
            __half2* dst = (__half2*)(g_Xh + i * 4);
            dst[0] = __floats2half2_rn(v.x, v.y);
            dst[1] = __floats2half2_rn(v.z, v.w);
        }
    } else if (b == 512 + nx) {
        if (tid < HIDDEN) {
            float s = gamma[tid] * rsqrtf(var[tid] + 1e-5f);
            g_ch[tid] = __float2half_rn(b1[tid] * s + beta[tid] - mean[tid] * s);
            g_w2h[tid] = __float2half_rn(W2[tid]);
        }
        if (tid < 32) {
            int acc = 0;
            for (int i = tid; i < 1024; i += 32) acc |= idx32[2 * i + 1];
            #pragma unroll
            for (int s = 16; s; s >>= 1) acc |= __shfl_xor_sync(0xFFFFFFFFu, acc, s);
            if (tid == 0) g_is64 = (acc == 0) ? 1 : 0;
        }
    } else {
        int zb = b - (513 + nx);
        int i = zb * 256 + tid;
        if (i < NROW_PAD) g_count[i] = 0;
    }
}

// ---------------------------------------------------------------------------
// Counting sort of edges by row node
// ---------------------------------------------------------------------------
__global__ void hist_kernel(const void* __restrict__ idx, int E) {
    int e = blockIdx.x * 256 + threadIdx.x;
    if (e >= E) return;
    int row = g_is64 ? (int)((const long long*)idx)[e] : ((const int*)idx)[e];
    atomicAdd(&g_count[row], 1);
}

__global__ void scanA_kernel(int M) {
    __shared__ int sd[256];
    int b = blockIdx.x;
    int tid = threadIdx.x;
    int i = b * 256 + tid;
    int v = (i <= M) ? g_count[i] : 0;
    sd[tid] = v;
    __syncthreads();
    #pragma unroll
    for (int off = 1; off < 256; off <<= 1) {
        int t = (tid >= off) ? sd[tid - off] : 0;
        __syncthreads();
        sd[tid] += t;
        __syncthreads();
    }
    g_pscan[i] = sd[tid] - v;   // exclusive within block
    if (tid == 255) g_blockSum[b] = sd[tid];
}

__global__ void scanB_kernel(int nb) {
    __shared__ int sd[256];
    int tid = threadIdx.x;
    int v = (tid < nb) ? g_blockSum[tid] : 0;
    sd[tid] = v;
    __syncthreads();
    #pragma unroll
    for (int off = 1; off < 256; off <<= 1) {
        int t = (tid >= off) ? sd[tid - off] : 0;
        __syncthreads();
        sd[tid] += t;
        __syncthreads();
    }
    g_blockOff[tid] = sd[tid] - v;
}

__global__ void scanC_kernel(int M) {
    int b = blockIdx.x;
    int i = b * 256 + threadIdx.x;
    if (i <= M) {
        int v = g_pscan[i] + g_blockOff[b];
        g_rowStart[i] = v;
        if (i < M) g_fill[i] = v;
    }
}

__global__ void scatter_kernel(const void* __restrict__ idx, int E) {
    int e = blockIdx.x * 256 + threadIdx.x;
    if (e >= E) return;
    int row, col;
    if (g_is64) {
        const long long* p = (const long long*)idx;
        row = (int)p[e]; col = (int)p[E + e];
    } else {
        const int* p = (const int*)idx;
        row = p[e]; col = p[E + e];
    }
    int pos = atomicAdd(&g_fill[row], 1);
    g_sCol[pos] = (uint32_t)col;
    g_sEid[pos] = e;
}

// ---------------------------------------------------------------------------
// Persistent warp-MMA fp16 GEMM (unchanged R9/R11 winner).
// ---------------------------------------------------------------------------
#define BM 128
#define BN 128
#define SM_B    0
#define SM_A    32768
#define A_STAGE 32768
#define SM_TOTAL 98304
#define STG_STRIDE 272

__global__ __launch_bounds__(256, 2) void gemm_mma_kernel(int M) {
    extern __shared__ char smem[];
    uint32_t sb = smem_u32(smem);
    int tid = threadIdx.x;
    int lane = tid & 31;
    int wid = tid >> 5;
    int wm = wid & 3;
    int wn = wid >> 2;
    int bn = blockIdx.x * BN;
    int y = blockIdx.y;
    int NY = gridDim.y;
    int totTiles = (M + BM - 1) / BM;

    for (int s = tid; s < 2048; s += 256) {
        int row = s >> 4;
        int c = s & 15;
        uint32_t off = (uint32_t)(row * 256 + ((c ^ (row & 7)) << 4));
        CP16(sb + SM_B + off, (const char*)(g_WTh + (size_t)(bn + row) * 128 + c * 8));
    }
    CP_COMMIT;

    auto prefetchA = [&](int t, int st) {
        int bm = t * BM;
        uint32_t base = sb + SM_A + st * A_STAGE;
        for (int s = tid; s < 2048; s += 256) {
            int row = s >> 4;
            int c = s & 15;
            int gr = bm + row;
            int valid = (gr < M) ? 1 : 0;
            uint32_t off = (uint32_t)(row * 256 + ((c ^ (row & 7)) << 4));
            CP16P(base + off, (const char*)(g_Xh + (size_t)gr * 128 + c * 8), valid);
        }
        CP_COMMIT;
    };

    if (y < totTiles) prefetchA(y, 0); else CP_COMMIT;

    int aR = (lane & 15);
    int aC = lane >> 4;
    int bR = (lane & 7) + ((lane >> 4) << 3);
    int bC = (lane >> 3) & 1;

    int i = 0;
    for (int t = y; t < totTiles; t += NY, i++) {
        int tn = t + NY;
        if (tn < totTiles) prefetchA(tn, (i + 1) & 1); else CP_COMMIT;
        CP_WAIT1;
        __syncthreads();

        uint32_t aBase = sb + SM_A + (i & 1) * A_STAGE;

        float acc[2][8][4];
        #pragma unroll
        for (int mt = 0; mt < 2; mt++)
            #pragma unroll
            for (int nt = 0; nt < 8; nt++)
                #pragma unroll
                for (int q = 0; q < 4; q++) acc[mt][nt][q] = 0.f;

        #pragma unroll
        for (int ks = 0; ks < 8; ks++) {
            uint32_t a[2][4], b[4][4];
            #pragma unroll
            for (int mt = 0; mt < 2; mt++) {
                int row = wm * 32 + mt * 16 + aR;
                int ch = ks * 2 + aC;
                uint32_t off = (uint32_t)(row * 256 + ((ch ^ (row & 7)) << 4));
                ldsm_x4(a[mt][0], a[mt][1], a[mt][2], a[mt][3], aBase + off);
            }
            #pragma unroll
            for (int np = 0; np < 4; np++) {
                int row = wn * 64 + np * 16 + bR;
                int ch = ks * 2 + bC;
                uint32_t off = (uint32_t)(row * 256 + ((ch ^ (row & 7)) << 4));
                ldsm_x4(b[np][0], b[np][1], b[np][2], b[np][3], sb + SM_B + off);
            }
            #pragma unroll
            for (int mt = 0; mt < 2; mt++)
                #pragma unroll
                for (int nt = 0; nt < 8; nt++) {
                    int np = nt >> 1, qp = (nt & 1) * 2;
                    mma16816(acc[mt][nt], a[mt], b[np][qp], b[np][qp + 1]);
                }
        }

        int bm = t * BM;
        char* stg = smem + SM_A + (i & 1) * A_STAGE;
        #pragma unroll
        for (int p = 0; p < 2; p++) {
            __syncthreads();
            if ((wm >> 1) == p) {
                int lrb = (wm & 1) * 32;
                #pragma unroll
                for (int mt = 0; mt < 2; mt++)
                    #pragma unroll
                    for (int h = 0; h < 2; h++) {
                        int lr = lrb + mt * 16 + (lane >> 2) + h * 8;
                        char* rowp = stg + lr * STG_STRIDE + wn * 128 + (lane & 3) * 4;
                        #pragma unroll
                        for (int nt = 0; nt < 8; nt++)
                            *(__half2*)(rowp + nt * 16) =
                                __floats2half2_rn(acc[mt][nt][h * 2], acc[mt][nt][h * 2 + 1]);
                    }
            }
            __syncthreads();
            for (int s = tid; s < 1024; s += 256) {
                int lr = s >> 4;
                int c = s & 15;
                int gr = bm + p * 64 + lr;
                if (gr < M)
                    *(uint4*)(g_table + (size_t)gr * NCOLS + bn + c * 8) =
                        *(const uint4*)(stg + lr * STG_STRIDE + c * 16);
            }
        }
        __syncthreads();
    }
}

// ---------------------------------------------------------------------------
// CSR edge kernel: one warp per row node. Row half (1KB) loaded once into
// registers; loop over that row's edges loads only the col half (1KB each).
// ---------------------------------------------------------------------------
__global__ __launch_bounds__(256) void edge_csr_kernel(const float* __restrict__ b2,
                                                       float* __restrict__ out, int M) {
    int w = (blockIdx.x * 256 + threadIdx.x) >> 5;
    if (w >= M) return;
    int lane = threadIdx.x & 31;

    int start = g_rowStart[w];
    int end = g_rowStart[w + 1];
    if (start == end) return;

    const char* tb = (const char*)g_table;
    uint32_t lo = (uint32_t)lane * 16u;
    uint32_t ro = (uint32_t)w * 2048u;

    uint4 r0 = *(const uint4*)(tb + ro + lo);          // seg0 (p1 row)
    uint4 r2 = *(const uint4*)(tb + ro + 512u + lo);   // seg2 (p2 row)
    uint4 ccv = ((const uint4*)g_ch)[lane];
    uint4 wwv = ((const uint4*)g_w2h)[lane];
    float bb = b2[0];

    const __half2* pr0 = (const __half2*)&r0;
    const __half2* pr2 = (const __half2*)&r2;
    const __half2* ch = (const __half2*)&ccv;
    const __half2* wh = (const __half2*)&wwv;
    const __half2 zero = __float2half2_rn(0.f);

    for (int j = start; j < end; j++) {
        uint32_t co = g_sCol[j] * 2048u;
        uint4 c1 = *(const uint4*)(tb + co + 1024u + lo);  // seg1 (p1 col)
        uint4 c3 = *(const uint4*)(tb + co + 1536u + lo);  // seg3 (p2 col)
        const __half2* pc1 = (const __half2*)&c1;
        const __half2* pc3 = (const __half2*)&c3;

        __half2 acc = zero;
        #pragma unroll
        for (int jj = 0; jj < 4; jj++) {
            __half2 z1 = __hadd2(__hadd2(pr0[jj], pc1[jj]), ch[jj]);
            acc = __hfma2(__hmax2(z1, zero), wh[jj], acc);
            __half2 z2 = __hadd2(__hadd2(pr2[jj], pc3[jj]), ch[jj]);
            acc = __hfma2(__hmax2(z2, zero), wh[jj], acc);
        }
        float2 f = __half22float2(acc);
        float s = f.x + f.y;
        #pragma unroll
        for (int sh = 16; sh; sh >>= 1) s += __shfl_xor_sync(0xFFFFFFFFu, s, sh);

        if (lane == 0) {
            float x = s * 0.5f + bb;
            out[g_sEid[j]] = 1.f / (1.f + expf(-x));
        }
    }
}

// ---------------------------------------------------------------------------
extern "C" void kernel_launch(void* const* d_in, const int* in_sizes, int n_in,
                              void* d_out, int out_size) {
    const float* node_feat = (const float*)d_in[0];
    const void*  eidx      = d_in[1];
    const float* W1        = (const float*)d_in[2];
    const float* b1        = (const float*)d_in[3];
    const float* gamma     = (const float*)d_in[4];
    const float* beta      = (const float*)d_in[5];
    const float* mean      = (const float*)d_in[6];
    const float* var       = (const float*)d_in[7];
    const float* W2        = (const float*)d_in[8];
    const float* b2        = (const float*)d_in[9];
    float* out = (float*)d_out;

    int M = in_sizes[0] / NODE_DIM;   // 50000
    int E = out_size;                 // 300000

    cudaFuncSetAttribute(gemm_mma_kernel, cudaFuncAttributeMaxDynamicSharedMemorySize, SM_TOTAL);

    int total4 = M * NODE_DIM / 4;
    int nx = (total4 + 255) / 256;
    int nzero = (NROW_PAD + 255) / 256;   // 197
    prep_all_kernel<<<513 + nx + nzero, 256>>>(node_feat, W1, b1, gamma, beta, mean, var, W2,
                                               (const int*)eidx, nx, total4);

    // counting sort by row node
    int nb = (M + 1 + 255) / 256;   // 196
    hist_kernel<<<(E + 255) / 256, 256>>>(eidx, E);
    scanA_kernel<<<nb, 256>>>(M);
    scanB_kernel<<<1, 256>>>(nb);
    scanC_kernel<<<nb, 256>>>(M);
    scatter_kernel<<<(E + 255) / 256, 256>>>(eidx, E);

    dim3 ggrid(NCOLS / BN, 36);   // 288 persistent CTAs, 2/SM
    gemm_mma_kernel<<<ggrid, 256, SM_TOTAL>>>(M);

    edge_csr_kernel<<<(M + 7) / 8, 256>>>(b2, out, M);
}

// round 15
// speedup vs baseline: 1.1310x; 1.1310x over previous
#include <cuda_runtime.h>
#include <cuda_fp16.h>
#include <cstdint>

#define N_NODES_MAX 50000
#define N_EDGES_MAX 524288
#define NODE_DIM    128
#define HIDDEN      256
#define NCOLS       1024
#define NROW_PAD    50432   // 197*256 >= N_NODES_MAX+1

// Table column layout: [0:256)=seg0 (p1 row), [256:512)=seg2 (p2 row),
//                      [512:768)=seg1 (p1 col), [768:1024)=seg3 (p2 col)

__device__ __half g_table[(size_t)N_NODES_MAX * NCOLS];   // 102.4 MB
__device__ __half g_Xh[(size_t)N_NODES_MAX * NODE_DIM];
__device__ __half g_WTh[NCOLS * NODE_DIM];
__device__ __half g_ch[HIDDEN];
__device__ __half g_w2h[HIDDEN];
__device__ int    g_is64;

// counting-sort scratch
__device__ int   g_count[NROW_PAD];
__device__ int   g_pscan[NROW_PAD];
__device__ int   g_rowStart[NROW_PAD];
__device__ int   g_fill[NROW_PAD];
__device__ int   g_blockSum[256];
__device__ int   g_blockOff[256];
__device__ uint2 g_sRC[N_EDGES_MAX];    // (row, col) sorted by row
__device__ int   g_sEid[N_EDGES_MAX];

__device__ __forceinline__ uint32_t smem_u32(const void* p) {
    uint32_t a;
    asm("{ .reg .u64 t; cvta.to.shared.u64 t, %1; cvt.u32.u64 %0, t; }" : "=r"(a) : "l"(p));
    return a;
}
__device__ __forceinline__ void ldsm_x4(uint32_t& r0, uint32_t& r1, uint32_t& r2, uint32_t& r3,
                                        uint32_t addr) {
    asm volatile("ldmatrix.sync.aligned.m8n8.x4.shared.b16 {%0,%1,%2,%3}, [%4];"
                 : "=r"(r0), "=r"(r1), "=r"(r2), "=r"(r3) : "r"(addr));
}
__device__ __forceinline__ void mma16816(float* c, const uint32_t* a, uint32_t b0, uint32_t b1) {
    asm volatile("mma.sync.aligned.m16n8k16.row.col.f32.f16.f16.f32 "
                 "{%0,%1,%2,%3}, {%4,%5,%6,%7}, {%8,%9}, {%0,%1,%2,%3};"
                 : "+f"(c[0]), "+f"(c[1]), "+f"(c[2]), "+f"(c[3])
                 : "r"(a[0]), "r"(a[1]), "r"(a[2]), "r"(a[3]), "r"(b0), "r"(b1));
}
#define CP16(dst, src) \
    asm volatile("cp.async.cg.shared.global [%0], [%1], 16;" :: "r"(dst), "l"(src))
#define CP16P(dst, src, p) \
    asm volatile("{ .reg .pred q; setp.ne.b32 q, %2, 0;\n\t" \
                 "@q cp.async.cg.shared.global [%0], [%1], 16; }" \
                 :: "r"(dst), "l"(src), "r"(p))
#define CP_COMMIT  asm volatile("cp.async.commit_group;")
#define CP_WAIT1   asm volatile("cp.async.wait_group 1;")

// ---------------------------------------------------------------------------
// prep (main stream): W fold, X->fp16, c/W2 half
// ---------------------------------------------------------------------------
__global__ void prep_all_kernel(const float* __restrict__ X,
                                const float* __restrict__ W1, const float* __restrict__ b1,
                                const float* __restrict__ gamma, const float* __restrict__ beta,
                                const float* __restrict__ mean, const float* __restrict__ var,
                                const float* __restrict__ W2, int nx, int total4) {
    int b = blockIdx.x;
    int tid = threadIdx.x;
    if (b < 512) {
        int i = b * 256 + tid;
        int n = i >> 7;
        int k = i & 127;
        int h = n & 255;
        int grp = n >> 8;
        int srcRow;
        if (grp == 0)      srcRow = k;
        else if (grp == 1) srcRow = k + 16;
        else if (grp == 2) srcRow = 128 + k;
        else               srcRow = (k + 144) & 255;
        float s = gamma[h] * rsqrtf(var[h] + 1e-5f);
        g_WTh[i] = __float2half_rn(W1[srcRow * 256 + h] * s);
    } else if (b < 512 + nx) {
        int i = (b - 512) * 256 + tid;
        if (i < total4) {
            float4 v = *(const float4*)(X + i * 4);
            __half2* dst = (__half2*)(g_Xh + i * 4);
            dst[0] = __floats2half2_rn(v.x, v.y);
            dst[1] = __floats2half2_rn(v.z, v.w);
        }
    } else {
        if (tid < HIDDEN) {
            float s = gamma[tid] * rsqrtf(var[tid] + 1e-5f);
            g_ch[tid] = __float2half_rn(b1[tid] * s + beta[tid] - mean[tid] * s);
            g_w2h[tid] = __float2half_rn(W2[tid]);
        }
    }
}

// ---------------------------------------------------------------------------
// Side chain: detect+zero, hist, 3-stage scan, scatter
// ---------------------------------------------------------------------------
__global__ void detect_zero_kernel(const int* __restrict__ idx32) {
    int b = blockIdx.x;
    int tid = threadIdx.x;
    if (b == 0) {
        if (tid < 32) {
            int acc = 0;
            for (int i = tid; i < 1024; i += 32) acc |= idx32[2 * i + 1];
            #pragma unroll
            for (int s = 16; s; s >>= 1) acc |= __shfl_xor_sync(0xFFFFFFFFu, acc, s);
            if (tid == 0) g_is64 = (acc == 0) ? 1 : 0;
        }
    } else {
        int i = (b - 1) * 256 + tid;
        if (i < NROW_PAD) g_count[i] = 0;
    }
}

__global__ void hist_kernel(const void* __restrict__ idx, int E) {
    int e = blockIdx.x * 256 + threadIdx.x;
    if (e >= E) return;
    int row = g_is64 ? (int)((const long long*)idx)[e] : ((const int*)idx)[e];
    atomicAdd(&g_count[row], 1);
}

__global__ void scanA_kernel(int M) {
    __shared__ int sd[256];
    int b = blockIdx.x;
    int tid = threadIdx.x;
    int i = b * 256 + tid;
    int v = (i <= M) ? g_count[i] : 0;
    sd[tid] = v;
    __syncthreads();
    #pragma unroll
    for (int off = 1; off < 256; off <<= 1) {
        int t = (tid >= off) ? sd[tid - off] : 0;
        __syncthreads();
        sd[tid] += t;
        __syncthreads();
    }
    g_pscan[i] = sd[tid] - v;
    if (tid == 255) g_blockSum[b] = sd[tid];
}

__global__ void scanB_kernel(int nb) {
    __shared__ int sd[256];
    int tid = threadIdx.x;
    int v = (tid < nb) ? g_blockSum[tid] : 0;
    sd[tid] = v;
    __syncthreads();
    #pragma unroll
    for (int off = 1; off < 256; off <<= 1) {
        int t = (tid >= off) ? sd[tid - off] : 0;
        __syncthreads();
        sd[tid] += t;
        __syncthreads();
    }
    g_blockOff[tid] = sd[tid] - v;
}

__global__ void scanC_kernel(int M) {
    int b = blockIdx.x;
    int i = b * 256 + threadIdx.x;
    if (i <= M) {
        int v = g_pscan[i] + g_blockOff[b];
        g_rowStart[i] = v;
        if (i < M) g_fill[i] = v;
    }
}

__global__ void scatter_kernel(const void* __restrict__ idx, int E) {
    int e = blockIdx.x * 256 + threadIdx.x;
    if (e >= E) return;
    int row, col;
    if (g_is64) {
        const long long* p = (const long long*)idx;
        row = (int)p[e]; col = (int)p[E + e];
    } else {
        const int* p = (const int*)idx;
        row = p[e]; col = p[E + e];
    }
    int pos = atomicAdd(&g_fill[row], 1);
    g_sRC[pos] = make_uint2((uint32_t)row, (uint32_t)col);
    g_sEid[pos] = e;
}

// ---------------------------------------------------------------------------
// Persistent warp-MMA fp16 GEMM (unchanged R9/R11 winner).
// ---------------------------------------------------------------------------
#define BM 128
#define BN 128
#define SM_B    0
#define SM_A    32768
#define A_STAGE 32768
#define SM_TOTAL 98304
#define STG_STRIDE 272

__global__ __launch_bounds__(256, 2) void gemm_mma_kernel(int M) {
    extern __shared__ char smem[];
    uint32_t sb = smem_u32(smem);
    int tid = threadIdx.x;
    int lane = tid & 31;
    int wid = tid >> 5;
    int wm = wid & 3;
    int wn = wid >> 2;
    int bn = blockIdx.x * BN;
    int y = blockIdx.y;
    int NY = gridDim.y;
    int totTiles = (M + BM - 1) / BM;

    for (int s = tid; s < 2048; s += 256) {
        int row = s >> 4;
        int c = s & 15;
        uint32_t off = (uint32_t)(row * 256 + ((c ^ (row & 7)) << 4));
        CP16(sb + SM_B + off, (const char*)(g_WTh + (size_t)(bn + row) * 128 + c * 8));
    }
    CP_COMMIT;

    auto prefetchA = [&](int t, int st) {
        int bm = t * BM;
        uint32_t base = sb + SM_A + st * A_STAGE;
        for (int s = tid; s < 2048; s += 256) {
            int row = s >> 4;
            int c = s & 15;
            int gr = bm + row;
            int valid = (gr < M) ? 1 : 0;
            uint32_t off = (uint32_t)(row * 256 + ((c ^ (row & 7)) << 4));
            CP16P(base + off, (const char*)(g_Xh + (size_t)gr * 128 + c * 8), valid);
        }
        CP_COMMIT;
    };

    if (y < totTiles) prefetchA(y, 0); else CP_COMMIT;

    int aR = (lane & 15);
    int aC = lane >> 4;
    int bR = (lane & 7) + ((lane >> 4) << 3);
    int bC = (lane >> 3) & 1;

    int i = 0;
    for (int t = y; t < totTiles; t += NY, i++) {
        int tn = t + NY;
        if (tn < totTiles) prefetchA(tn, (i + 1) & 1); else CP_COMMIT;
        CP_WAIT1;
        __syncthreads();

        uint32_t aBase = sb + SM_A + (i & 1) * A_STAGE;

        float acc[2][8][4];
        #pragma unroll
        for (int mt = 0; mt < 2; mt++)
            #pragma unroll
            for (int nt = 0; nt < 8; nt++)
                #pragma unroll
                for (int q = 0; q < 4; q++) acc[mt][nt][q] = 0.f;

        #pragma unroll
        for (int ks = 0; ks < 8; ks++) {
            uint32_t a[2][4], b[4][4];
            #pragma unroll
            for (int mt = 0; mt < 2; mt++) {
                int row = wm * 32 + mt * 16 + aR;
                int ch = ks * 2 + aC;
                uint32_t off = (uint32_t)(row * 256 + ((ch ^ (row & 7)) << 4));
                ldsm_x4(a[mt][0], a[mt][1], a[mt][2], a[mt][3], aBase + off);
            }
            #pragma unroll
            for (int np = 0; np < 4; np++) {
                int row = wn * 64 + np * 16 + bR;
                int ch = ks * 2 + bC;
                uint32_t off = (uint32_t)(row * 256 + ((ch ^ (row & 7)) << 4));
                ldsm_x4(b[np][0], b[np][1], b[np][2], b[np][3], sb + SM_B + off);
            }
            #pragma unroll
            for (int mt = 0; mt < 2; mt++)
                #pragma unroll
                for (int nt = 0; nt < 8; nt++) {
                    int np = nt >> 1, qp = (nt & 1) * 2;
                    mma16816(acc[mt][nt], a[mt], b[np][qp], b[np][qp + 1]);
                }
        }

        int bm = t * BM;
        char* stg = smem + SM_A + (i & 1) * A_STAGE;
        #pragma unroll
        for (int p = 0; p < 2; p++) {
            __syncthreads();
            if ((wm >> 1) == p) {
                int lrb = (wm & 1) * 32;
                #pragma unroll
                for (int mt = 0; mt < 2; mt++)
                    #pragma unroll
                    for (int h = 0; h < 2; h++) {
                        int lr = lrb + mt * 16 + (lane >> 2) + h * 8;
                        char* rowp = stg + lr * STG_STRIDE + wn * 128 + (lane & 3) * 4;
                        #pragma unroll
                        for (int nt = 0; nt < 8; nt++)
                            *(__half2*)(rowp + nt * 16) =
                                __floats2half2_rn(acc[mt][nt][h * 2], acc[mt][nt][h * 2 + 1]);
                    }
            }
            __syncthreads();
            for (int s = tid; s < 1024; s += 256) {
                int lr = s >> 4;
                int c = s & 15;
                int gr = bm + p * 64 + lr;
                if (gr < M)
                    *(uint4*)(g_table + (size_t)gr * NCOLS + bn + c * 8) =
                        *(const uint4*)(stg + lr * STG_STRIDE + c * 16);
            }
        }
        __syncthreads();
    }
}

// ---------------------------------------------------------------------------
// Edge kernel: R11 shape (2 edges/warp, 8 gathers upfront) on ROW-SORTED
// edges -> row halves hit L1 within a block, cutting LTS bytes ~40%.
// ---------------------------------------------------------------------------
__global__ void edge_sorted_kernel(const float* __restrict__ b2,
                                   float* __restrict__ out, int E) {
    int lane = threadIdx.x & 31;
    int e0 = blockIdx.x * 16 + (threadIdx.x >> 5) * 2;
    if (e0 >= E) return;
    bool has2 = (e0 + 1 < E);
    int e1 = has2 ? e0 + 1 : e0;

    uint2 rc0 = g_sRC[e0];
    uint2 rc1 = g_sRC[e1];
    uint32_t or0 = rc0.x * 2048u, oc0 = rc0.y * 2048u;
    uint32_t or1 = rc1.x * 2048u, oc1 = rc1.y * 2048u;

    const char* tb = (const char*)g_table;
    uint32_t lo = (uint32_t)lane * 16u;

    uint4 a0 = *(const uint4*)(tb + or0 + lo);
    uint4 a2 = *(const uint4*)(tb + or0 + 512u + lo);
    uint4 b1v = *(const uint4*)(tb + oc0 + 1024u + lo);
    uint4 b3 = *(const uint4*)(tb + oc0 + 1536u + lo);
    uint4 d0 = *(const uint4*)(tb + or1 + lo);
    uint4 d2 = *(const uint4*)(tb + or1 + 512u + lo);
    uint4 f1 = *(const uint4*)(tb + oc1 + 1024u + lo);
    uint4 f3 = *(const uint4*)(tb + oc1 + 1536u + lo);

    uint4 ccv = ((const uint4*)g_ch)[lane];
    uint4 wwv = ((const uint4*)g_w2h)[lane];

    const __half2* ch = (const __half2*)&ccv;
    const __half2* wh = (const __half2*)&wwv;
    const __half2* pa0 = (const __half2*)&a0;  const __half2* pa2 = (const __half2*)&a2;
    const __half2* pb1 = (const __half2*)&b1v; const __half2* pb3 = (const __half2*)&b3;
    const __half2* pd0 = (const __half2*)&d0;  const __half2* pd2 = (const __half2*)&d2;
    const __half2* pf1 = (const __half2*)&f1;  const __half2* pf3 = (const __half2*)&f3;

    const __half2 zero = __float2half2_rn(0.f);
    __half2 accA = zero, accB = zero;
    #pragma unroll
    for (int j = 0; j < 4; j++) {
        __half2 z1 = __hadd2(__hadd2(pa0[j], pb1[j]), ch[j]);
        accA = __hfma2(__hmax2(z1, zero), wh[j], accA);
        __half2 z2 = __hadd2(__hadd2(pa2[j], pb3[j]), ch[j]);
        accA = __hfma2(__hmax2(z2, zero), wh[j], accA);
        __half2 y1 = __hadd2(__hadd2(pd0[j], pf1[j]), ch[j]);
        accB = __hfma2(__hmax2(y1, zero), wh[j], accB);
        __half2 y2 = __hadd2(__hadd2(pd2[j], pf3[j]), ch[j]);
        accB = __hfma2(__hmax2(y2, zero), wh[j], accB);
    }
    float2 fA = __half22float2(accA);
    float2 fB = __half22float2(accB);
    float sA = fA.x + fA.y;
    float sB = fB.x + fB.y;

    #pragma unroll
    for (int s = 16; s; s >>= 1) {
        sA += __shfl_xor_sync(0xFFFFFFFFu, sA, s);
        sB += __shfl_xor_sync(0xFFFFFFFFu, sB, s);
    }

    if (lane == 0) {
        float bb = b2[0];
        float x = sA * 0.5f + bb;
        out[g_sEid[e0]] = 1.f / (1.f + expf(-x));
        if (has2) {
            float x2 = sB * 0.5f + bb;
            out[g_sEid[e1]] = 1.f / (1.f + expf(-x2));
        }
    }
}

// ---------------------------------------------------------------------------
extern "C" void kernel_launch(void* const* d_in, const int* in_sizes, int n_in,
                              void* d_out, int out_size) {
    const float* node_feat = (const float*)d_in[0];
    const void*  eidx      = d_in[1];
    const float* W1        = (const float*)d_in[2];
    const float* b1        = (const float*)d_in[3];
    const float* gamma     = (const float*)d_in[4];
    const float* beta      = (const float*)d_in[5];
    const float* mean      = (const float*)d_in[6];
    const float* var       = (const float*)d_in[7];
    const float* W2        = (const float*)d_in[8];
    const float* b2        = (const float*)d_in[9];
    float* out = (float*)d_out;

    int M = in_sizes[0] / NODE_DIM;   // 50000
    int E = out_size;                 // 300000

    // one-time host resources for the forked capture branch
    static cudaStream_t s_side = nullptr;
    static cudaEvent_t s_evA = nullptr, s_evB = nullptr;
    if (s_side == nullptr) {
        cudaStreamCreateWithFlags(&s_side, cudaStreamNonBlocking);
        cudaEventCreateWithFlags(&s_evA, cudaEventDisableTiming);
        cudaEventCreateWithFlags(&s_evB, cudaEventDisableTiming);
    }

    cudaFuncSetAttribute(gemm_mma_kernel, cudaFuncAttributeMaxDynamicSharedMemorySize, SM_TOTAL);

    int total4 = M * NODE_DIM / 4;
    int nx = (total4 + 255) / 256;
    int nb = (M + 1 + 255) / 256;          // 196 scan blocks
    int nzero = (NROW_PAD + 255) / 256;    // 197

    // fork side stream (sort chain), independent of prep/gemm
    cudaEventRecord(s_evA, 0);
    cudaStreamWaitEvent(s_side, s_evA, 0);
    detect_zero_kernel<<<1 + nzero, 256, 0, s_side>>>((const int*)eidx);
    hist_kernel<<<(E + 255) / 256, 256, 0, s_side>>>(eidx, E);
    scanA_kernel<<<nb, 256, 0, s_side>>>(M);
    scanB_kernel<<<1, 256, 0, s_side>>>(nb);
    scanC_kernel<<<nb, 256, 0, s_side>>>(M);
    scatter_kernel<<<(E + 255) / 256, 256, 0, s_side>>>(eidx, E);
    cudaEventRecord(s_evB, s_side);

    // main stream: prep + GEMM
    prep_all_kernel<<<513 + nx, 256>>>(node_feat, W1, b1, gamma, beta, mean, var, W2,
                                       nx, total4);
    dim3 ggrid(NCOLS / BN, 36);
    gemm_mma_kernel<<<ggrid, 256, SM_TOTAL>>>(M);

    // join, then edge
    cudaStreamWaitEvent(0, s_evB, 0);
    edge_sorted_kernel<<<(E + 15) / 16, 256>>>(b2, out, E);
}

// round 16
// speedup vs baseline: 1.2296x; 1.0872x over previous
#include <cuda_runtime.h>
#include <cuda_fp16.h>
#include <cstdint>

#define N_NODES_MAX 50000
#define NODE_DIM    128
#define HIDDEN      256
#define NCOLS       1024

// Table column layout: [0:256)=seg0 (p1 row), [256:512)=seg2 (p2 row),
//                      [512:768)=seg1 (p1 col), [768:1024)=seg3 (p2 col)

__device__ __half g_table[(size_t)N_NODES_MAX * NCOLS];   // 102.4 MB
__device__ __half g_Xh[(size_t)N_NODES_MAX * NODE_DIM];   // 12.8 MB
__device__ __half g_WTh[NCOLS * NODE_DIM];                // [n][k] permuted
__device__ __half g_ch[HIDDEN];
__device__ __half g_w2h[HIDDEN];
__device__ int    g_is64;

__device__ __forceinline__ uint32_t smem_u32(const void* p) {
    uint32_t a;
    asm("{ .reg .u64 t; cvta.to.shared.u64 t, %1; cvt.u32.u64 %0, t; }" : "=r"(a) : "l"(p));
    return a;
}
__device__ __forceinline__ void ldsm_x4(uint32_t& r0, uint32_t& r1, uint32_t& r2, uint32_t& r3,
                                        uint32_t addr) {
    asm volatile("ldmatrix.sync.aligned.m8n8.x4.shared.b16 {%0,%1,%2,%3}, [%4];"
                 : "=r"(r0), "=r"(r1), "=r"(r2), "=r"(r3) : "r"(addr));
}
// fp16-accumulate MMA: D,C are 2 regs (4 halves) — 2x rate vs f32 acc on mma.sync
__device__ __forceinline__ void mma16816_h(uint32_t* c, const uint32_t* a,
                                           uint32_t b0, uint32_t b1) {
    asm volatile("mma.sync.aligned.m16n8k16.row.col.f16.f16.f16.f16 "
                 "{%0,%1}, {%2,%3,%4,%5}, {%6,%7}, {%0,%1};"
                 : "+r"(c[0]), "+r"(c[1])
                 : "r"(a[0]), "r"(a[1]), "r"(a[2]), "r"(a[3]), "r"(b0), "r"(b1));
}
#define CP16(dst, src) \
    asm volatile("cp.async.cg.shared.global [%0], [%1], 16;" :: "r"(dst), "l"(src))
#define CP16P(dst, src, p) \
    asm volatile("{ .reg .pred q; setp.ne.b32 q, %2, 0;\n\t" \
                 "@q cp.async.cg.shared.global [%0], [%1], 16; }" \
                 :: "r"(dst), "l"(src), "r"(p))
#define CP_COMMIT  asm volatile("cp.async.commit_group;")
#define CP_WAIT1   asm volatile("cp.async.wait_group 1;")

// ---------------------------------------------------------------------------
// Fused prep (R11 version)
// ---------------------------------------------------------------------------
__global__ void prep_all_kernel(const float* __restrict__ X,
                                const float* __restrict__ W1, const float* __restrict__ b1,
                                const float* __restrict__ gamma, const float* __restrict__ beta,
                                const float* __restrict__ mean, const float* __restrict__ var,
                                const float* __restrict__ W2,
                                const int* __restrict__ idx32, int nx, int total4) {
    int b = blockIdx.x;
    int tid = threadIdx.x;
    if (b < 512) {
        int i = b * 256 + tid;
        int n = i >> 7;
        int k = i & 127;
        int h = n & 255;
        int grp = n >> 8;
        int srcRow;
        if (grp == 0)      srcRow = k;
        else if (grp == 1) srcRow = k + 16;
        else if (grp == 2) srcRow = 128 + k;
        else               srcRow = (k + 144) & 255;
        float s = gamma[h] * rsqrtf(var[h] + 1e-5f);
        g_WTh[i] = __float2half_rn(W1[srcRow * 256 + h] * s);
    } else if (b < 512 + nx) {
        int i = (b - 512) * 256 + tid;
        if (i < total4) {
            float4 v = *(const float4*)(X + i * 4);
            __half2* dst = (__half2*)(g_Xh + i * 4);
            dst[0] = __floats2half2_rn(v.x, v.y);
            dst[1] = __floats2half2_rn(v.z, v.w);
        }
    } else {
        if (tid < HIDDEN) {
            float s = gamma[tid] * rsqrtf(var[tid] + 1e-5f);
            g_ch[tid] = __float2half_rn(b1[tid] * s + beta[tid] - mean[tid] * s);
            g_w2h[tid] = __float2half_rn(W2[tid]);
        }
        if (tid < 32) {
            int acc = 0;
            for (int i = tid; i < 1024; i += 32) acc |= idx32[2 * i + 1];
            #pragma unroll
            for (int s = 16; s; s >>= 1) acc |= __shfl_xor_sync(0xFFFFFFFFu, acc, s);
            if (tid == 0) g_is64 = (acc == 0) ? 1 : 0;
        }
    }
}

// ---------------------------------------------------------------------------
// Persistent warp-MMA fp16 GEMM with fp16 ACCUMULATORS (2x HMMA rate).
// ---------------------------------------------------------------------------
#define BM 128
#define BN 128
#define SM_B    0
#define SM_A    32768
#define A_STAGE 32768
#define SM_TOTAL 98304
#define STG_STRIDE 272

__global__ __launch_bounds__(256, 2) void gemm_mma_kernel(int M) {
    extern __shared__ char smem[];
    uint32_t sb = smem_u32(smem);
    int tid = threadIdx.x;
    int lane = tid & 31;
    int wid = tid >> 5;
    int wm = wid & 3;
    int wn = wid >> 2;
    int bn = blockIdx.x * BN;
    int y = blockIdx.y;
    int NY = gridDim.y;
    int totTiles = (M + BM - 1) / BM;

    for (int s = tid; s < 2048; s += 256) {
        int row = s >> 4;
        int c = s & 15;
        uint32_t off = (uint32_t)(row * 256 + ((c ^ (row & 7)) << 4));
        CP16(sb + SM_B + off, (const char*)(g_WTh + (size_t)(bn + row) * 128 + c * 8));
    }
    CP_COMMIT;

    auto prefetchA = [&](int t, int st) {
        int bm = t * BM;
        uint32_t base = sb + SM_A + st * A_STAGE;
        for (int s = tid; s < 2048; s += 256) {
            int row = s >> 4;
            int c = s & 15;
            int gr = bm + row;
            int valid = (gr < M) ? 1 : 0;
            uint32_t off = (uint32_t)(row * 256 + ((c ^ (row & 7)) << 4));
            CP16P(base + off, (const char*)(g_Xh + (size_t)gr * 128 + c * 8), valid);
        }
        CP_COMMIT;
    };

    if (y < totTiles) prefetchA(y, 0); else CP_COMMIT;

    int aR = (lane & 15);
    int aC = lane >> 4;
    int bR = (lane & 7) + ((lane >> 4) << 3);
    int bC = (lane >> 3) & 1;

    int i = 0;
    for (int t = y; t < totTiles; t += NY, i++) {
        int tn = t + NY;
        if (tn < totTiles) prefetchA(tn, (i + 1) & 1); else CP_COMMIT;
        CP_WAIT1;
        __syncthreads();

        uint32_t aBase = sb + SM_A + (i & 1) * A_STAGE;

        // fp16 accumulators: [mt][nt] = 2 regs (half2 x2)
        uint32_t acc[2][8][2];
        #pragma unroll
        for (int mt = 0; mt < 2; mt++)
            #pragma unroll
            for (int nt = 0; nt < 8; nt++) {
                acc[mt][nt][0] = 0u;
                acc[mt][nt][1] = 0u;
            }

        #pragma unroll
        for (int ks = 0; ks < 8; ks++) {
            uint32_t a[2][4], b[4][4];
            #pragma unroll
            for (int mt = 0; mt < 2; mt++) {
                int row = wm * 32 + mt * 16 + aR;
                int ch = ks * 2 + aC;
                uint32_t off = (uint32_t)(row * 256 + ((ch ^ (row & 7)) << 4));
                ldsm_x4(a[mt][0], a[mt][1], a[mt][2], a[mt][3], aBase + off);
            }
            #pragma unroll
            for (int np = 0; np < 4; np++) {
                int row = wn * 64 + np * 16 + bR;
                int ch = ks * 2 + bC;
                uint32_t off = (uint32_t)(row * 256 + ((ch ^ (row & 7)) << 4));
                ldsm_x4(b[np][0], b[np][1], b[np][2], b[np][3], sb + SM_B + off);
            }
            #pragma unroll
            for (int mt = 0; mt < 2; mt++)
                #pragma unroll
                for (int nt = 0; nt < 8; nt++) {
                    int np = nt >> 1, qp = (nt & 1) * 2;
                    mma16816_h(acc[mt][nt], a[mt], b[np][qp], b[np][qp + 1]);
                }
        }

        int bm = t * BM;
        char* stg = smem + SM_A + (i & 1) * A_STAGE;
        #pragma unroll
        for (int p = 0; p < 2; p++) {
            __syncthreads();
            if ((wm >> 1) == p) {
                int lrb = (wm & 1) * 32;
                #pragma unroll
                for (int mt = 0; mt < 2; mt++)
                    #pragma unroll
                    for (int h = 0; h < 2; h++) {
                        int lr = lrb + mt * 16 + (lane >> 2) + h * 8;
                        char* rowp = stg + lr * STG_STRIDE + wn * 128 + (lane & 3) * 4;
                        #pragma unroll
                        for (int nt = 0; nt < 8; nt++)
                            *(uint32_t*)(rowp + nt * 16) = acc[mt][nt][h];
                    }
            }
            __syncthreads();
            for (int s = tid; s < 1024; s += 256) {
                int lr = s >> 4;
                int c = s & 15;
                int gr = bm + p * 64 + lr;
                if (gr < M)
                    *(uint4*)(g_table + (size_t)gr * NCOLS + bn + c * 8) =
                        *(const uint4*)(stg + lr * STG_STRIDE + c * 16);
            }
        }
        __syncthreads();
    }
}

// ---------------------------------------------------------------------------
// Edge kernel: R11 champion shape — 2 edges/warp, ALL 8 gathers upfront,
// packed half2 MLP.
// ---------------------------------------------------------------------------
__global__ __launch_bounds__(256) void edge_kernel(const void* __restrict__ idx,
                                                   const float* __restrict__ b2,
                                                   float* __restrict__ out, int E) {
    int lane = threadIdx.x & 31;
    int e0 = blockIdx.x * 16 + (threadIdx.x >> 5) * 2;
    if (e0 >= E) return;
    bool has2 = (e0 + 1 < E);
    int e1 = has2 ? e0 + 1 : e0;

    int r0, c0, r1, c1;
    if (g_is64) {
        const long long* p = (const long long*)idx;
        r0 = (int)p[e0]; c0 = (int)p[E + e0];
        r1 = (int)p[e1]; c1 = (int)p[E + e1];
    } else {
        const int* p = (const int*)idx;
        r0 = p[e0]; c0 = p[E + e0];
        r1 = p[e1]; c1 = p[E + e1];
    }

    const __half* Tr0 = g_table + (size_t)r0 * NCOLS;
    const __half* Tc0 = g_table + (size_t)c0 * NCOLS;
    const __half* Tr1 = g_table + (size_t)r1 * NCOLS;
    const __half* Tc1 = g_table + (size_t)c1 * NCOLS;
    int o = lane * 8;

    uint4 a0 = *(const uint4*)(Tr0 + o);
    uint4 a2 = *(const uint4*)(Tr0 + 256 + o);
    uint4 b1v = *(const uint4*)(Tc0 + 512 + o);
    uint4 b3 = *(const uint4*)(Tc0 + 768 + o);
    uint4 d0 = *(const uint4*)(Tr1 + o);
    uint4 d2 = *(const uint4*)(Tr1 + 256 + o);
    uint4 f1 = *(const uint4*)(Tc1 + 512 + o);
    uint4 f3 = *(const uint4*)(Tc1 + 768 + o);

    uint4 chv = *(const uint4*)(g_ch + o);
    uint4 whv = *(const uint4*)(g_w2h + o);

    const __half2* ch = (const __half2*)&chv;
    const __half2* wh = (const __half2*)&whv;
    const __half2* pa0 = (const __half2*)&a0;  const __half2* pa2 = (const __half2*)&a2;
    const __half2* pb1 = (const __half2*)&b1v; const __half2* pb3 = (const __half2*)&b3;
    const __half2* pd0 = (const __half2*)&d0;  const __half2* pd2 = (const __half2*)&d2;
    const __half2* pf1 = (const __half2*)&f1;  const __half2* pf3 = (const __half2*)&f3;

    const __half2 zero = __float2half2_rn(0.f);
    __half2 accA = zero, accB = zero;
    #pragma unroll
    for (int j = 0; j < 4; j++) {
        __half2 z1 = __hadd2(__hadd2(pa0[j], pb1[j]), ch[j]);
        accA = __hfma2(__hmax2(z1, zero), wh[j], accA);
        __half2 z2 = __hadd2(__hadd2(pa2[j], pb3[j]), ch[j]);
        accA = __hfma2(__hmax2(z2, zero), wh[j], accA);
        __half2 y1 = __hadd2(__hadd2(pd0[j], pf1[j]), ch[j]);
        accB = __hfma2(__hmax2(y1, zero), wh[j], accB);
        __half2 y2 = __hadd2(__hadd2(pd2[j], pf3[j]), ch[j]);
        accB = __hfma2(__hmax2(y2, zero), wh[j], accB);
    }
    float2 fA = __half22float2(accA);
    float2 fB = __half22float2(accB);
    float sA = fA.x + fA.y;
    float sB = fB.x + fB.y;

    #pragma unroll
    for (int s = 16; s; s >>= 1) {
        sA += __shfl_xor_sync(0xFFFFFFFFu, sA, s);
        sB += __shfl_xor_sync(0xFFFFFFFFu, sB, s);
    }

    if (lane == 0) {
        float bb = b2[0];
        float x = sA * 0.5f + bb;
        out[e0] = 1.f / (1.f + expf(-x));
        if (has2) {
            float x2 = sB * 0.5f + bb;
            out[e0 + 1] = 1.f / (1.f + expf(-x2));
        }
    }
}

// ---------------------------------------------------------------------------
extern "C" void kernel_launch(void* const* d_in, const int* in_sizes, int n_in,
                              void* d_out, int out_size) {
    const float* node_feat = (const float*)d_in[0];
    const void*  eidx      = d_in[1];
    const float* W1        = (const float*)d_in[2];
    const float* b1        = (const float*)d_in[3];
    const float* gamma     = (const float*)d_in[4];
    const float* beta      = (const float*)d_in[5];
    const float* mean      = (const float*)d_in[6];
    const float* var       = (const float*)d_in[7];
    const float* W2        = (const float*)d_in[8];
    const float* b2        = (const float*)d_in[9];
    float* out = (float*)d_out;

    int M = in_sizes[0] / NODE_DIM;   // 50000
    int E = out_size;                 // 300000

    cudaFuncSetAttribute(gemm_mma_kernel, cudaFuncAttributeMaxDynamicSharedMemorySize, SM_TOTAL);

    int total4 = M * NODE_DIM / 4;
    int nx = (total4 + 255) / 256;
    prep_all_kernel<<<513 + nx, 256>>>(node_feat, W1, b1, gamma, beta, mean, var, W2,
                                       (const int*)eidx, nx, total4);

    dim3 ggrid(NCOLS / BN, 37);   // (8,37) = 296 CTAs -> 2/SM on all 148 SMs
    gemm_mma_kernel<<<ggrid, 256, SM_TOTAL>>>(M);

    edge_kernel<<<(E + 15) / 16, 256>>>(eidx, b2, out, E);
}